// round 5
// baseline (speedup 1.0000x reference)
#include <cuda_runtime.h>
#include <cstdint>

#define BB 4
#define NN 16384
#define MM 1024

// ---- static scratch (no allocation) ----
__device__ float  g_support[BB*NN*32];
__device__ float4 g_filt[BB*NN];
__device__ int    g_cidx[BB*MM];
__device__ float  g_cent[BB*MM*32];
__device__ unsigned long long g_best3[BB][3];
__device__ unsigned int g_arr[BB];
__device__ int    g_bidx[2*BB*MM*64];
__device__ int    g_bcnt[2*BB*MM];
__device__ float  g_att[2*BB*MM*32];
__device__ float  g_h1[2*BB*MM*64];
__device__ float  g_h2[2*BB*MM*128];
__device__ float  g_s1a[2*64], g_s2a[2*64], g_s1b[2*128], g_s2b[2*128];
__device__ float  g_A1[2*64], g_C1[2*64], g_A2[2*128], g_C2[2*128];

__global__ void k_init() {
    int t = threadIdx.x;
    if (t < 12)  ((unsigned long long*)g_best3)[t] = 0ull;
    if (t < 4)   g_arr[t] = 0u;
    if (t < 128) { g_s1a[t] = 0.f; g_s2a[t] = 0.f; }
    if (t < 256) { g_s1b[t] = 0.f; g_s2b[t] = 0.f; }
}

// transpose [B,32,N] channel-major inputs -> point-major support + 4-dim filter
__global__ __launch_bounds__(256) void k_build(const float* __restrict__ xyz,
                                               const float* __restrict__ pf) {
    __shared__ float t[32][33];
    int b  = blockIdx.x >> 9;
    int n0 = (blockIdx.x & 511) << 5;
    int tid = threadIdx.x;
#pragma unroll
    for (int i = 0; i < 4; i++) {
        int e = tid + i*256, c = e >> 5, n = e & 31;
        float v = (c < 3) ? xyz[(b*3 + c)*NN + n0 + n] : pf[(b*29 + (c-3))*NN + n0 + n];
        t[n][c] = v;
    }
    __syncthreads();
    int n = tid >> 3, c0 = (tid & 7) << 2;
    *(float4*)&g_support[((size_t)(b*NN + n0 + n))*32 + c0] =
        make_float4(t[n][c0], t[n][c0+1], t[n][c0+2], t[n][c0+3]);
    if (tid < 32)
        g_filt[b*NN + n0 + tid] = make_float4(t[tid][3], t[tid][4], t[tid][5], t[tid][6]);
}

// FPS: persistent, 16 blocks/batch, 2 points x 32 dims in registers per thread
__global__ void __launch_bounds__(512, 1) k_fps() {
    int b = blockIdx.x >> 4, blk = blockIdx.x & 15, tid = threadIdx.x;
    __shared__ unsigned long long sred[16];
    __shared__ int sf;
    int p0 = (blk << 10) + tid, p1 = p0 + 512;
    float x0[32], x1[32];
    {
        const float4* a = (const float4*)&g_support[(size_t)(b*NN + p0)*32];
        const float4* c = (const float4*)&g_support[(size_t)(b*NN + p1)*32];
#pragma unroll
        for (int i = 0; i < 8; i++) {
            float4 v = a[i]; x0[4*i]=v.x; x0[4*i+1]=v.y; x0[4*i+2]=v.z; x0[4*i+3]=v.w;
            float4 u = c[i]; x1[4*i]=u.x; x1[4*i+1]=u.y; x1[4*i+2]=u.z; x1[4*i+3]=u.w;
        }
    }
    float d0 = 1e10f, d1 = 1e10f;
    int f = 0;
    for (int t = 0; t < MM; t++) {
        if (blk == 0 && tid == 0) g_cidx[b*MM + t] = f;
        const float4* cp = (const float4*)&g_support[(size_t)(b*NN + f)*32];
        float a0=0.f, a1=0.f, c0=0.f, c1=0.f;
#pragma unroll
        for (int i = 0; i < 8; i++) {
            float4 cv = cp[i]; float e;
            e = x0[4*i]  -cv.x; a0 = fmaf(e,e,a0);
            e = x1[4*i]  -cv.x; a1 = fmaf(e,e,a1);
            e = x0[4*i+1]-cv.y; c0 = fmaf(e,e,c0);
            e = x1[4*i+1]-cv.y; c1 = fmaf(e,e,c1);
            e = x0[4*i+2]-cv.z; a0 = fmaf(e,e,a0);
            e = x1[4*i+2]-cv.z; a1 = fmaf(e,e,a1);
            e = x0[4*i+3]-cv.w; c0 = fmaf(e,e,c0);
            e = x1[4*i+3]-cv.w; c1 = fmaf(e,e,c1);
        }
        d0 = fminf(d0, a0 + c0);
        d1 = fminf(d1, a1 + c1);
        float dm; unsigned pi;
        if (d0 >= d1) { dm = d0; pi = (unsigned)p0; } else { dm = d1; pi = (unsigned)p1; }
        unsigned long long pk = ((unsigned long long)__float_as_uint(dm) << 32)
                              | (unsigned long long)(0xFFFFFFFFu - pi);  // tie -> lowest idx
#pragma unroll
        for (int o = 16; o; o >>= 1) {
            unsigned long long q = __shfl_down_sync(0xFFFFFFFFu, pk, o);
            if (q > pk) pk = q;
        }
        if ((tid & 31) == 0) sred[tid >> 5] = pk;
        __syncthreads();
        if (tid < 32) {
            unsigned long long pk2 = (tid < 16) ? sred[tid] : 0ull;
#pragma unroll
            for (int o = 8; o; o >>= 1) {
                unsigned long long q = __shfl_down_sync(0xFFFFFFFFu, pk2, o);
                if (q > pk2) pk2 = q;
            }
            if (tid == 0) {
                atomicMax(&g_best3[b][t % 3], pk2);
                if (blk == 0) atomicExch(&g_best3[b][(t + 1) % 3], 0ull);
                __threadfence();
                atomicAdd(&g_arr[b], 1u);
                unsigned target = 16u * (unsigned)(t + 1);
                while (*((volatile unsigned int*)&g_arr[b]) < target) {}
                __threadfence();
                unsigned long long w = atomicAdd(&g_best3[b][t % 3], 0ull);
                sf = (int)(0xFFFFFFFFu - (unsigned)(w & 0xFFFFFFFFull));
            }
        }
        __syncthreads();
        f = sf;
    }
}

__global__ __launch_bounds__(256) void k_gather(float* __restrict__ out) {
    int gt = blockIdx.x * 256 + threadIdx.x;
    int bm = gt >> 5, lane = gt & 31;
    int b = bm >> 10, m = bm & 1023;
    int ci = g_cidx[bm];
    float v = g_support[(size_t)(b*NN + ci)*32 + lane];
    g_cent[bm*32 + lane] = v;
    if (lane < 3) out[(b*3 + lane)*MM + m] = v;
}

// ball query: 4-dim lower-bound prune, exact 32-dim verify for survivors
__global__ __launch_bounds__(256) void k_ball(float r2, int kmax, int s) {
    int w = threadIdx.x >> 5, lane = threadIdx.x & 31;
    int bm = blockIdx.x * 8 + w;
    int b = bm >> 10;
    const float* cen = &g_cent[bm*32];
    float c3 = cen[3], c4 = cen[4], c5 = cen[5], c6 = cen[6];
    int cnt = 0;
    int* outIdx = &g_bidx[(size_t)(s*4096 + bm)*64];
    const float4* filt = &g_filt[b*NN];
    for (int it = 0; it < NN/32; it++) {
        int n = (it << 5) + lane;
        float4 fv = filt[n];
        float dx = fv.x - c3; float d4 = dx*dx;
        dx = fv.y - c4; d4 = fmaf(dx, dx, d4);
        dx = fv.z - c5; d4 = fmaf(dx, dx, d4);
        dx = fv.w - c6; d4 = fmaf(dx, dx, d4);
        bool pred = false;
        if (d4 <= r2) {
            const float* pp = &g_support[(size_t)(b*NN + n)*32];
            float dd = 0.f;
#pragma unroll
            for (int i = 0; i < 32; i++) { float e = pp[i] - cen[i]; dd = fmaf(e, e, dd); }
            pred = (dd <= r2);
        }
        unsigned bal = __ballot_sync(0xFFFFFFFFu, pred);
        while (bal && cnt < kmax) {
            int l = __ffs(bal) - 1; bal &= bal - 1;
            if (lane == 0) outIdx[cnt] = (it << 5) + l;
            cnt++;
        }
        if (cnt >= kmax) break;
    }
    if (lane == 0) g_bcnt[s*4096 + bm] = cnt;
}

// attention over unmasked neighbors only (masked softmax weights are exactly 0)
__global__ __launch_bounds__(256) void k_att(const float* __restrict__ wq,
                                             const float* __restrict__ wk,
                                             const float* __restrict__ wv,
                                             const float* __restrict__ wo, int s) {
    __shared__ float s_q[32*64], s_k[32*64], s_v[32*64], s_oT[64*32];
    __shared__ float s_x[8][32], s_y[8][32], s_o[8][64], s_l[8][128];
    int tid = threadIdx.x;
    for (int i = tid; i < 2048; i += 256) {
        int oc = i >> 5, c = i & 31;
        s_q[c*64 + oc] = wq[i];
        s_k[c*64 + oc] = wk[i];
        s_v[c*64 + oc] = wv[i];
        int oc2 = i >> 6, c2 = i & 63;
        s_oT[c2*32 + oc2] = wo[i];
    }
    __syncthreads();
    int w = tid >> 5, lane = tid & 31;
    int bm = blockIdx.x * 8 + w;
    int b = bm >> 10;
    float xv = g_cent[bm*32 + lane];
    s_x[w][lane] = xv;
    __syncwarp();
    float q0 = 0.f, q1 = 0.f;
#pragma unroll
    for (int c = 0; c < 32; c++) {
        float xc = s_x[w][c];
        q0 = fmaf(s_q[c*64 + lane],      xc, q0);
        q1 = fmaf(s_q[c*64 + 32 + lane], xc, q1);
    }
    int cnt = g_bcnt[s*4096 + bm];
    const int* bidx = &g_bidx[(size_t)(s*4096 + bm)*64];
    const float rs = 0.17677669529663687f;  // 1/sqrt(32)
    for (int j = 0; j < cnt; j++) {
        int id = bidx[j];
        float yv = g_support[(size_t)(b*NN + id)*32 + lane] - s_x[w][lane];
        s_y[w][lane] = yv; __syncwarp();
        float k0 = 0.f, k1 = 0.f;
#pragma unroll
        for (int c = 0; c < 32; c++) {
            float yc = s_y[w][c];
            k0 = fmaf(s_k[c*64 + lane],      yc, k0);
            k1 = fmaf(s_k[c*64 + 32 + lane], yc, k1);
        }
        float l0 = q0*k0, l1 = q1*k1;
#pragma unroll
        for (int o = 16; o; o >>= 1) {
            l0 += __shfl_xor_sync(0xFFFFFFFFu, l0, o);
            l1 += __shfl_xor_sync(0xFFFFFFFFu, l1, o);
        }
        if (lane == 0) { s_l[w][j] = l0*rs; s_l[w][64 + j] = l1*rs; }
        __syncwarp();
    }
#pragma unroll
    for (int h = 0; h < 2; h++) {
        float v0 = (lane      < cnt) ? s_l[w][h*64 + lane]      : -3e38f;
        float v1 = (lane + 32 < cnt) ? s_l[w][h*64 + lane + 32] : -3e38f;
        float mx = fmaxf(v0, v1);
#pragma unroll
        for (int o = 16; o; o >>= 1) mx = fmaxf(mx, __shfl_xor_sync(0xFFFFFFFFu, mx, o));
        float e0 = (lane      < cnt) ? __expf(v0 - mx) : 0.f;
        float e1 = (lane + 32 < cnt) ? __expf(v1 - mx) : 0.f;
        float sm = e0 + e1;
#pragma unroll
        for (int o = 16; o; o >>= 1) sm += __shfl_xor_sync(0xFFFFFFFFu, sm, o);
        float inv = 1.f / sm;
        if (lane      < cnt) s_l[w][h*64 + lane]      = e0 * inv;
        if (lane + 32 < cnt) s_l[w][h*64 + lane + 32] = e1 * inv;
    }
    __syncwarp();
    float o0 = 0.f, o1 = 0.f;
    for (int j = 0; j < cnt; j++) {
        int id = bidx[j];
        float yv = g_support[(size_t)(b*NN + id)*32 + lane] - s_x[w][lane];
        s_y[w][lane] = yv; __syncwarp();
        float v0 = 0.f, v1 = 0.f;
#pragma unroll
        for (int c = 0; c < 32; c++) {
            float yc = s_y[w][c];
            v0 = fmaf(s_v[c*64 + lane],      yc, v0);
            v1 = fmaf(s_v[c*64 + 32 + lane], yc, v1);
        }
        o0 = fmaf(s_l[w][j],      v0, o0);
        o1 = fmaf(s_l[w][64 + j], v1, o1);
        __syncwarp();
    }
    s_o[w][lane] = o0; s_o[w][32 + lane] = o1; __syncwarp();
    float outv = s_x[w][lane];
#pragma unroll
    for (int c = 0; c < 64; c++) outv = fmaf(s_oT[c*32 + lane], s_o[w][c], outv);
    g_att[(size_t)(s*4096 + bm)*32 + lane] = outv;
}

__global__ __launch_bounds__(256) void k_mlp1(const float* __restrict__ W0,
                                              const float* __restrict__ b0, int s) {
    __shared__ float sW[32*64];
    __shared__ float s_in[4][32];
    __shared__ float sh[4][64];
    int tid = threadIdx.x;
    for (int i = tid; i < 2048; i += 256) { int oc = i >> 5, c = i & 31; sW[c*64 + oc] = W0[i]; }
    int bm0 = blockIdx.x * 4;
    if (tid < 128) s_in[tid >> 5][tid & 31] = g_att[(size_t)(s*4096 + bm0)*32 + tid];
    __syncthreads();
    int oc = tid & 63, q = tid >> 6;
    float h = b0[oc];
#pragma unroll
    for (int c = 0; c < 32; c++) h = fmaf(sW[c*64 + oc], s_in[q][c], h);
    g_h1[(size_t)(s*4096 + bm0 + q)*64 + oc] = h;
    sh[q][oc] = h;
    __syncthreads();
    if (q == 0) {
        float s1 = 0.f, s2 = 0.f;
#pragma unroll
        for (int qq = 0; qq < 4; qq++) { float v = sh[qq][oc]; s1 += v; s2 = fmaf(v, v, s2); }
        atomicAdd(&g_s1a[s*64 + oc], s1);
        atomicAdd(&g_s2a[s*64 + oc], s2);
    }
}

__global__ void k_fin1(const float* __restrict__ g, const float* __restrict__ beta, int s) {
    int oc = threadIdx.x;
    float mu  = g_s1a[s*64 + oc] * (1.f/4096.f);
    float var = g_s2a[s*64 + oc] * (1.f/4096.f) - mu*mu;
    float A = g[oc] * rsqrtf(var + 1e-5f);
    g_A1[s*64 + oc] = A;
    g_C1[s*64 + oc] = beta[oc] - mu*A;
}

__global__ __launch_bounds__(256) void k_mlp2(const float* __restrict__ W1,
                                              const float* __restrict__ b1, int s) {
    __shared__ float sW[64*128];
    __shared__ float sact[2][64];
    __shared__ float sh[2][128];
    int tid = threadIdx.x;
    for (int i = tid; i < 8192; i += 256) { int oc = i >> 6, c = i & 63; sW[c*128 + oc] = W1[i]; }
    int bm0 = blockIdx.x * 2;
    if (tid < 128) {
        int q = tid >> 6, c = tid & 63;
        float v = g_h1[(size_t)(s*4096 + bm0 + q)*64 + c];
        v = g_A1[s*64 + c]*v + g_C1[s*64 + c];
        sact[q][c] = v > 0.f ? v : 0.02f*v;
    }
    __syncthreads();
    int oc = tid & 127, q = tid >> 7;
    float h = b1[oc];
#pragma unroll
    for (int c = 0; c < 64; c++) h = fmaf(sW[c*128 + oc], sact[q][c], h);
    g_h2[(size_t)(s*4096 + bm0 + q)*128 + oc] = h;
    sh[q][oc] = h;
    __syncthreads();
    if (q == 0) {
        float a = sh[0][oc], bb = sh[1][oc];
        atomicAdd(&g_s1b[s*128 + oc], a + bb);
        atomicAdd(&g_s2b[s*128 + oc], fmaf(a, a, bb*bb));
    }
}

__global__ void k_fin2(const float* __restrict__ g, const float* __restrict__ beta, int s) {
    int oc = threadIdx.x;
    float mu  = g_s1b[s*128 + oc] * (1.f/4096.f);
    float var = g_s2b[s*128 + oc] * (1.f/4096.f) - mu*mu;
    float A = g[oc] * rsqrtf(var + 1e-5f);
    g_A2[s*128 + oc] = A;
    g_C2[s*128 + oc] = beta[oc] - mu*A;
}

__global__ __launch_bounds__(256) void k_out(float* __restrict__ out, int s) {
    int idx = blockIdx.x * 256 + threadIdx.x;
    int m = idx & 1023;
    int t2 = idx >> 10;
    int oc = t2 & 127, b = t2 >> 7;
    int bm = b*1024 + m;
    float v = g_h2[(size_t)(s*4096 + bm)*128 + oc];
    v = g_A2[s*128 + oc]*v + g_C2[s*128 + oc];
    out[12288 + (((b*256) + s*128 + oc) << 10) + m] = v;
}

extern "C" void kernel_launch(void* const* d_in, const int* in_sizes, int n_in,
                              void* d_out, int out_size) {
    (void)in_sizes; (void)n_in; (void)out_size;
    const float* xyz = (const float*)d_in[0];
    const float* pf  = (const float*)d_in[1];
    float* out = (float*)d_out;
    k_init<<<1, 256>>>();
    k_build<<<2048, 256>>>(xyz, pf);
    k_fps<<<64, 512>>>();
    k_gather<<<512, 256>>>(out);
    const float r2s[2] = {0.1f*0.1f, 0.2f*0.2f};
    const int   kms[2] = {32, 64};
    for (int s = 0; s < 2; s++) {
        int o = 2 + s*12;
        k_ball<<<512, 256>>>(r2s[s], kms[s], s);
        k_att<<<512, 256>>>((const float*)d_in[o],   (const float*)d_in[o+1],
                            (const float*)d_in[o+2], (const float*)d_in[o+3], s);
        k_mlp1<<<1024, 256>>>((const float*)d_in[o+4], (const float*)d_in[o+5], s);
        k_fin1<<<1, 64>>>((const float*)d_in[o+6], (const float*)d_in[o+7], s);
        k_mlp2<<<2048, 256>>>((const float*)d_in[o+8], (const float*)d_in[o+9], s);
        k_fin2<<<1, 128>>>((const float*)d_in[o+10], (const float*)d_in[o+11], s);
        k_out<<<2048, 256>>>(out, s);
    }
}